// round 7
// baseline (speedup 1.0000x reference)
#include <cuda_runtime.h>
#include <cuda_bf16.h>
#include <cstdint>

// 3x3 cross-correlation, 4096x4096 fp32, pad=1, stride=1.
// out[i][j] = sum_{dr,dc} w[dr*3+dc] * x[i+dr-1][j+dc-1] + bias
//
// Rolling-accumulator (low-register) + distance-2 prefetch:
//  - warp strip = 128 wide x 16 rows; lane owns 4 consecutive cols.
//  - per input row: 1 LDG.128 (+2 lane-edge scalars), 2 SHFL, 36 FMA, 12 FADD,
//    1 streaming STG.128. Input row g feeds output rows g-1,g,g+1 via three
//    rolling float4 accumulators -> only ~50 live regs -> 40 warps/SM.
//  - raw buffers pfA/pfB: LDG issued 2 iterations before use -> no exposed
//    DRAM latency at 40 warps/SM.

#define N_IMG 4096
#define TW    128
#define RPT   16
#define WARPS 8
#define TILE_H (RPT * WARPS)   // 128 rows per CTA
#define FULLMASK 0xFFFFFFFFu

struct Raw { float4 v; float e; };

__device__ __forceinline__ Raw fetch_fast(const float* __restrict__ x,
                                          int grow, int c0, int lane)
{
    const float* rowp = x + (size_t)grow * N_IMG;
    Raw r;
    r.v = *reinterpret_cast<const float4*>(rowp + c0);
    r.e = 0.f;
    if (lane == 0)  r.e = rowp[c0 - 1];
    if (lane == 31) r.e = rowp[c0 + 4];
    return r;
}

__device__ __forceinline__ Raw fetch_guard(const float* __restrict__ x,
                                           int grow, int c0, int lane)
{
    Raw r;
    r.v = make_float4(0.f, 0.f, 0.f, 0.f);
    r.e = 0.f;
    if ((unsigned)grow < (unsigned)N_IMG) {   // warp-uniform
        const float* rowp = x + (size_t)grow * N_IMG;
        r.v = *reinterpret_cast<const float4*>(rowp + c0);
        if (lane == 0 && c0 > 0)          r.e = rowp[c0 - 1];
        if (lane == 31 && c0 + 4 < N_IMG) r.e = rowp[c0 + 4];
    }
    return r;
}

template<bool GUARD>
__device__ __forceinline__ void do_strip(const float* __restrict__ x,
                                         float* __restrict__ out,
                                         int row0, int tile_x, int lane,
                                         const float* w, float b)
{
    const int c0 = tile_x + lane * 4;

    float4 accP = make_float4(b, b, b, b);
    float4 accQ = make_float4(b, b, b, b);

    Raw pfA, pfB;
    if (GUARD) {
        pfA = fetch_guard(x, row0 - 1, c0, lane);
        pfB = fetch_guard(x, row0,     c0, lane);
    } else {
        pfA = fetch_fast(x, row0 - 1, c0, lane);
        pfB = fetch_fast(x, row0,     c0, lane);
    }

    #pragma unroll
    for (int i = -1; i <= RPT; i++) {
        // expand pfA = input row (row0+i) into 6-wide shifted window
        float lf = __shfl_up_sync(FULLMASK, pfA.v.w, 1);
        float rt = __shfl_down_sync(FULLMASK, pfA.v.x, 1);
        if (lane == 0)  lf = pfA.e;
        if (lane == 31) rt = pfA.e;
        const float v0 = lf,      v1 = pfA.v.x, v2 = pfA.v.y;
        const float v3 = pfA.v.z, v4 = pfA.v.w, v5 = rt;
        pfA = pfB;

        // prefetch row (row0+i+2); last needed input row is row0+RPT
        if (i + 2 <= RPT) {
            if (GUARD) pfB = fetch_guard(x, row0 + i + 2, c0, lane);
            else       pfB = fetch_fast (x, row0 + i + 2, c0, lane);
        }

        // horizontal 3-tap per weight row (input cols c-1..c+2 per output c)
        float h0x = fmaf(w[0],v0, fmaf(w[1],v1, w[2]*v2));
        float h0y = fmaf(w[0],v1, fmaf(w[1],v2, w[2]*v3));
        float h0z = fmaf(w[0],v2, fmaf(w[1],v3, w[2]*v4));
        float h0w = fmaf(w[0],v3, fmaf(w[1],v4, w[2]*v5));

        float h1x = fmaf(w[3],v0, fmaf(w[4],v1, w[5]*v2));
        float h1y = fmaf(w[3],v1, fmaf(w[4],v2, w[5]*v3));
        float h1z = fmaf(w[3],v2, fmaf(w[4],v3, w[5]*v4));
        float h1w = fmaf(w[3],v3, fmaf(w[4],v4, w[5]*v5));

        float h2x = fmaf(w[6],v0, fmaf(w[7],v1, w[8]*v2));
        float h2y = fmaf(w[6],v1, fmaf(w[7],v2, w[8]*v3));
        float h2z = fmaf(w[6],v2, fmaf(w[7],v3, w[8]*v4));
        float h2w = fmaf(w[6],v3, fmaf(w[7],v4, w[8]*v5));

        // input row g: h2 -> out g-1 (accP), h1 -> out g (accQ), h0 -> out g+1
        accP.x += h2x; accP.y += h2y; accP.z += h2z; accP.w += h2w;
        accQ.x += h1x; accQ.y += h1y; accQ.z += h1z; accQ.w += h1w;
        float4 accR = make_float4(b + h0x, b + h0y, b + h0z, b + h0w);

        if (i >= 1) {   // accP = completed output row row0+i-1
            __stcs(reinterpret_cast<float4*>(
                out + (size_t)(row0 + i - 1) * N_IMG + c0), accP);
        }

        accP = accQ;
        accQ = accR;
    }
}

__global__ __launch_bounds__(256, 5)
void conv3x3_roll2_kernel(const float* __restrict__ x,
                          const float* __restrict__ w9,
                          const float* __restrict__ bias,
                          float* __restrict__ out)
{
    const int lane   = threadIdx.x & 31;
    const int warp   = threadIdx.x >> 5;
    const int tile_x = blockIdx.x * TW;
    const int row0   = blockIdx.y * TILE_H + warp * RPT;

    float w[9];
    #pragma unroll
    for (int i = 0; i < 9; i++) w[i] = __ldg(&w9[i]);
    const float b = __ldg(&bias[0]);

    // interior fast path touches rows row0-1 .. row0+RPT, cols tile_x-1 .. tile_x+TW
    const bool guard = (row0 == 0) | (row0 + RPT >= N_IMG) |
                       (tile_x == 0) | (tile_x + TW >= N_IMG);

    if (!guard)
        do_strip<false>(x, out, row0, tile_x, lane, w, b);
    else
        do_strip<true >(x, out, row0, tile_x, lane, w, b);
}

extern "C" void kernel_launch(void* const* d_in, const int* in_sizes, int n_in,
                              void* d_out, int out_size)
{
    const float* x    = (const float*)d_in[0];   // 4096*4096
    const float* w9   = (const float*)d_in[1];   // 9
    const float* bias = (const float*)d_in[2];   // 1
    float* out        = (float*)d_out;           // 4096*4096

    dim3 block(256, 1, 1);
    dim3 grid(N_IMG / TW, N_IMG / TILE_H, 1);    // 32 x 32 = 1024 CTAs
    conv3x3_roll2_kernel<<<grid, block>>>(x, w9, bias, out);
}